// round 1
// baseline (speedup 1.0000x reference)
#include <cuda_runtime.h>
#include <math.h>

#define BATCH   8
#define SEQ     200
#define NNODES  512
#define HID     64
#define NEDGES  2048
#define ALPHA   0.2f
#define NEGBIG  -9.0e15f

// ---------------- scratch (device globals, no allocation) ----------------
__device__ float g_h0[BATCH * NNODES * HID];
__device__ float g_Wh[BATCH * NNODES * HID];
__device__ float g_h1[BATCH * NNODES * HID];
__device__ float g_h2[BATCH * NNODES * HID];
__device__ float g_f1[BATCH * NNODES];
__device__ float g_f2[BATCH * NNODES];

// ---------------- Stage A: fused conv1+relu+conv2+relu+mean ----------------
// One block per (b, n). 256 threads.
// Shared: s_in[2][208] (padded), s_h1[32][208] (padded), s_w2 transposed
// [(ic*5+k)*64 + oc], s_w1[320], s_red[64*8].
#define S_IN_OFF   0
#define S_H1_OFF   (2 * 208)
#define S_W2_OFF   (S_H1_OFF + 32 * 208)
#define S_W1_OFF   (S_W2_OFF + 10240)
#define S_RED_OFF  (S_W1_OFF + 320)
#define CONV_SMEM_FLOATS (S_RED_OFF + 64 * 8)
#define CONV_SMEM_BYTES  (CONV_SMEM_FLOATS * 4)

__global__ void __launch_bounds__(256, 2)
conv_fused_kernel(const float* __restrict__ x,
                  const float* __restrict__ w1, const float* __restrict__ b1,
                  const float* __restrict__ w2, const float* __restrict__ b2,
                  float* __restrict__ h0)
{
    extern __shared__ float sm[];
    float* s_in  = sm + S_IN_OFF;
    float* s_h1  = sm + S_H1_OFF;
    float* s_w2  = sm + S_W2_OFF;
    float* s_w1  = sm + S_W1_OFF;
    float* s_red = sm + S_RED_OFF;

    const int bn  = blockIdx.x;
    const int b   = bn >> 9;
    const int n   = bn & 511;
    const int tid = threadIdx.x;

    // zero padded input + h1 regions
    for (int i = tid; i < 2 * 208; i += 256)  s_in[i] = 0.f;
    for (int i = tid; i < 32 * 208; i += 256) s_h1[i] = 0.f;

    // load weights
    for (int i = tid; i < 320; i += 256) s_w1[i] = w1[i];
    for (int i = tid; i < 10240; i += 256) {
        int oc = i / 160;
        int r  = i - oc * 160;             // r = ic*5 + k
        s_w2[r * 64 + oc] = w2[i];
    }
    __syncthreads();   // ensure s_in zeros visible before partial fill ordering

    // load input: xf[bn][c][s] = x[b, s, 2n + c]
    const float* xb = x + (size_t)b * SEQ * (NNODES * 2) + 2 * n;
    for (int i = tid; i < 2 * SEQ; i += 256) {
        int s = i >> 1, c = i & 1;
        s_in[c * 208 + 2 + s] = xb[(size_t)s * (NNODES * 2) + c];
    }
    __syncthreads();

    // conv1: 32 oc x 200 pos, kernel 5, 2 in channels
    for (int i = tid; i < 32 * SEQ; i += 256) {
        int oc = i / SEQ, s = i - oc * SEQ;
        const float* w  = s_w1 + oc * 10;
        const float* i0 = s_in + s;
        const float* i1 = s_in + 208 + s;
        float acc = b1[oc];
#pragma unroll
        for (int k = 0; k < 5; k++)
            acc = fmaf(w[k], i0[k], fmaf(w[5 + k], i1[k], acc));
        s_h1[oc * 208 + 2 + s] = fmaxf(acc, 0.f);
    }
    __syncthreads();

    // conv2 + relu + sum over positions
    // thread = (ocg, sg): oc = 2*ocg (2 output channels), s in [25*sg, 25*sg+25)
    const int ocg = tid & 31;
    const int sg  = tid >> 5;
    const int oc0 = ocg * 2;
    const int s0  = sg * 25;

    float acc0[25], acc1[25];
#pragma unroll
    for (int p = 0; p < 25; p++) { acc0[p] = 0.f; acc1[p] = 0.f; }

    for (int ic = 0; ic < 32; ic++) {
        float hw[29];
        const float* hrow = s_h1 + ic * 208 + s0;
#pragma unroll
        for (int j = 0; j < 29; j++) hw[j] = hrow[j];
        const float* wrow = s_w2 + ic * 5 * 64 + oc0;
#pragma unroll
        for (int k = 0; k < 5; k++) {
            float wa = wrow[k * 64];
            float wb = wrow[k * 64 + 1];
#pragma unroll
            for (int p = 0; p < 25; p++) {
                acc0[p] = fmaf(wa, hw[p + k], acc0[p]);
                acc1[p] = fmaf(wb, hw[p + k], acc1[p]);
            }
        }
    }
    const float bias0 = b2[oc0], bias1 = b2[oc0 + 1];
    float sum0 = 0.f, sum1 = 0.f;
#pragma unroll
    for (int p = 0; p < 25; p++) {
        sum0 += fmaxf(acc0[p] + bias0, 0.f);
        sum1 += fmaxf(acc1[p] + bias1, 0.f);
    }
    s_red[oc0 * 8 + sg]       = sum0;
    s_red[(oc0 + 1) * 8 + sg] = sum1;
    __syncthreads();

    if (tid < 64) {
        float t = 0.f;
#pragma unroll
        for (int r = 0; r < 8; r++) t += s_red[tid * 8 + r];
        h0[(size_t)bn * HID + tid] = t * (1.f / 200.f);
    }
}

// ---------------- Stage B: Wh = h @ W ; f1 = Wh@a[:64] ; f2 = Wh@a[64:] ----
// block = 256 threads = 4 rows x 64 dims ; grid = 4096/4 = 1024
__global__ void __launch_bounds__(256)
gat_pre_kernel(const float* __restrict__ h, const float* __restrict__ W,
               const float* __restrict__ a,
               float* __restrict__ Wh, float* __restrict__ f1, float* __restrict__ f2)
{
    __shared__ float sW[64 * 64];
    __shared__ float sh[4 * 64];
    __shared__ float s1[8], s2[8];

    const int tid  = threadIdx.x;
    const int row0 = blockIdx.x * 4;

    for (int i = tid; i < 64 * 64; i += 256) sW[i] = W[i];
    sh[tid] = h[(size_t)row0 * 64 + tid];
    __syncthreads();

    const int r = tid >> 6;
    const int d = tid & 63;
    const float* hr = sh + r * 64;
    float acc = 0.f;
#pragma unroll
    for (int k = 0; k < 64; k++) acc = fmaf(hr[k], sW[k * 64 + d], acc);
    Wh[(size_t)(row0 + r) * 64 + d] = acc;

    float v1 = acc * a[d];
    float v2 = acc * a[64 + d];
#pragma unroll
    for (int o = 16; o; o >>= 1) {
        v1 += __shfl_down_sync(0xffffffffu, v1, o);
        v2 += __shfl_down_sync(0xffffffffu, v2, o);
    }
    if ((tid & 31) == 0) { s1[tid >> 5] = v1; s2[tid >> 5] = v2; }
    __syncthreads();
    if (tid < 4) {
        f1[row0 + tid] = s1[2 * tid] + s1[2 * tid + 1];
        f2[row0 + tid] = s2[2 * tid] + s2[2 * tid + 1];
    }
}

// ---------------- Stage C: attention row ----------------
// block per (b, i), 128 threads.
__global__ void __launch_bounds__(128)
gat_att_kernel(const float* __restrict__ Wh, const float* __restrict__ f1,
               const float* __restrict__ f2, const int* __restrict__ adj,
               float* __restrict__ out, int do_relu)
{
    __shared__ float sp[512];
    __shared__ float swr[4];
    __shared__ float sacc[128];

    const int bi  = blockIdx.x;
    const int b   = bi >> 9;
    const int i   = bi & 511;
    const int tid = threadIdx.x;

    const float f1i = f1[bi];
    const float* f2b = f2 + b * NNODES;
    const int* adjrow = adj + (size_t)i * NNODES;

    // pass 1: e (leaky + mask), running max
    float lmax = -3.4e38f;
#pragma unroll
    for (int jj = 0; jj < 4; jj++) {
        int j = tid + jj * 128;
        float e = f1i + f2b[j];
        e = (e > 0.f) ? e : ALPHA * e;
        e = (adjrow[j] > 0) ? e : NEGBIG;
        sp[j] = e;
        lmax = fmaxf(lmax, e);
    }
#pragma unroll
    for (int o = 16; o; o >>= 1)
        lmax = fmaxf(lmax, __shfl_xor_sync(0xffffffffu, lmax, o));
    if ((tid & 31) == 0) swr[tid >> 5] = lmax;
    __syncthreads();
    const float gmax = fmaxf(fmaxf(swr[0], swr[1]), fmaxf(swr[2], swr[3]));
    __syncthreads();

    // pass 2: exp, running sum
    float lsum = 0.f;
#pragma unroll
    for (int jj = 0; jj < 4; jj++) {
        int j = tid + jj * 128;
        float p = expf(sp[j] - gmax);
        sp[j] = p;
        lsum += p;
    }
#pragma unroll
    for (int o = 16; o; o >>= 1)
        lsum += __shfl_xor_sync(0xffffffffu, lsum, o);
    if ((tid & 31) == 0) swr[tid >> 5] = lsum;
    __syncthreads();
    const float gsum = swr[0] + swr[1] + swr[2] + swr[3];
    __syncthreads();   // sp fully written before pass 3 cross-thread reads

    // pass 3: acc_d = sum_j p_j * Wh[b,j,d], split j range across two halves
    const int half = tid >> 6;
    const int d    = tid & 63;
    const float* Whb = Wh + (size_t)b * NNODES * HID;
    float acc = 0.f;
    const int j0 = half * 256;
#pragma unroll 8
    for (int j = j0; j < j0 + 256; j++)
        acc = fmaf(sp[j], Whb[(size_t)j * HID + d], acc);
    sacc[tid] = acc;
    __syncthreads();

    if (tid < 64) {
        float v = (sacc[tid] + sacc[tid + 64]) / gsum;
        if (do_relu) v = fmaxf(v, 0.f);
        out[(size_t)bi * HID + tid] = v;
    }
}

// ---------------- Stage D: edge gather + MLP + sigmoid ----------------
// grid (2048, 8), 64 threads
__global__ void __launch_bounds__(64)
edge_mlp_kernel(const float* __restrict__ h, const int* __restrict__ eidx,
                const float* __restrict__ fc1w, const float* __restrict__ fc1b,
                const float* __restrict__ fc2w, const float* __restrict__ fc2b,
                float* __restrict__ out)
{
    __shared__ float she[128];
    __shared__ float sr[2];

    const int e   = blockIdx.x;
    const int b   = blockIdx.y;
    const int tid = threadIdx.x;

    const int i1 = eidx[2 * e];
    const int i2 = eidx[2 * e + 1];
    she[tid]      = h[((size_t)b * NNODES + i1) * HID + tid];
    she[64 + tid] = h[((size_t)b * NNODES + i2) * HID + tid];
    __syncthreads();

    float acc = fc1b[tid];
#pragma unroll 8
    for (int k = 0; k < 128; k++)
        acc = fmaf(she[k], fc1w[(size_t)k * 64 + tid], acc);
    acc = fmaxf(acc, 0.f);

    float v = acc * fc2w[tid];
#pragma unroll
    for (int o = 16; o; o >>= 1)
        v += __shfl_down_sync(0xffffffffu, v, o);
    if ((tid & 31) == 0) sr[tid >> 5] = v;
    __syncthreads();
    if (tid == 0) {
        float z = sr[0] + sr[1] + fc2b[0];
        out[(size_t)b * NEDGES + e] = 1.f / (1.f + expf(-z));
    }
}

// ---------------- launch ----------------
extern "C" void kernel_launch(void* const* d_in, const int* in_sizes, int n_in,
                              void* d_out, int out_size)
{
    const float* x    = (const float*)d_in[0];
    const int*   adj  = (const int*)  d_in[1];
    const int*   eidx = (const int*)  d_in[2];
    const float* w1   = (const float*)d_in[3];
    const float* b1   = (const float*)d_in[4];
    const float* w2   = (const float*)d_in[5];
    const float* b2   = (const float*)d_in[6];
    const float* W1   = (const float*)d_in[7];
    const float* a1   = (const float*)d_in[8];
    const float* W2   = (const float*)d_in[9];
    const float* a2   = (const float*)d_in[10];
    const float* fc1w = (const float*)d_in[11];
    const float* fc1b = (const float*)d_in[12];
    const float* fc2w = (const float*)d_in[13];
    const float* fc2b = (const float*)d_in[14];
    float* out = (float*)d_out;

    float *h0, *Wh, *h1, *h2, *f1, *f2;
    cudaGetSymbolAddress((void**)&h0, g_h0);
    cudaGetSymbolAddress((void**)&Wh, g_Wh);
    cudaGetSymbolAddress((void**)&h1, g_h1);
    cudaGetSymbolAddress((void**)&h2, g_h2);
    cudaGetSymbolAddress((void**)&f1, g_f1);
    cudaGetSymbolAddress((void**)&f2, g_f2);

    cudaFuncSetAttribute(conv_fused_kernel,
                         cudaFuncAttributeMaxDynamicSharedMemorySize,
                         CONV_SMEM_BYTES);

    // Stage A: per-node temporal conv feature extractor
    conv_fused_kernel<<<BATCH * NNODES, 256, CONV_SMEM_BYTES>>>(x, w1, b1, w2, b2, h0);

    // GAT layer 1 (relu on output)
    gat_pre_kernel<<<(BATCH * NNODES) / 4, 256>>>(h0, W1, a1, Wh, f1, f2);
    gat_att_kernel<<<BATCH * NNODES, 128>>>(Wh, f1, f2, adj, h1, 1);

    // GAT layer 2 (no relu)
    gat_pre_kernel<<<(BATCH * NNODES) / 4, 256>>>(h1, W2, a2, Wh, f1, f2);
    gat_att_kernel<<<BATCH * NNODES, 128>>>(Wh, f1, f2, adj, h2, 0);

    // Edge MLP
    dim3 eg(NEDGES, BATCH);
    edge_mlp_kernel<<<eg, 64>>>(h2, eidx, fc1w, fc1b, fc2w, fc2b, out);
}